// round 1
// baseline (speedup 1.0000x reference)
#include <cuda_runtime.h>

// Shapes (fixed):
//  input_tensor: (8, 3, 256, 256)   d_in[0]
//  conv1_w:      (8, 3, 1, 1)       d_in[1]
//  conv1_b:      (8,)               d_in[2]
//  offset_w:     (27, 8, 3, 3)      d_in[3]
//  offset_b:     (27,)              d_in[4]
//  dcn_w:        (512, 8, 3, 3)     d_in[5]
//  out:          (8, 512, 128, 128) float32

#define NB   8
#define HH   256
#define WW   256
#define CC   8
#define HO   128
#define WO   128
#define NPOS (NB * HO * WO)      // 131072
#define NTILES (NPOS / 32)       // 4096
#define NSLICE 148

// scratch (device globals; no allocation allowed)
__device__ float g_y[NB * HH * WW * CC];        // [n][h][w][c]  16 MB, channels-last
__device__ float g_off[NB * 27 * HO * WO];      // [n][ch][sp]   14 MB

typedef unsigned long long u64;

__device__ __forceinline__ u64 pack2(float lo, float hi) {
    u64 r; asm("mov.b64 %0, {%1, %2};" : "=l"(r) : "f"(lo), "f"(hi)); return r;
}
__device__ __forceinline__ void fma2(u64& d, u64 a, u64 b) {
    asm("fma.rn.f32x2 %0, %1, %2, %0;" : "+l"(d) : "l"(a), "l"(b));
}
__device__ __forceinline__ void unpack2(u64 v, float& lo, float& hi) {
    asm("mov.b64 {%0, %1}, %2;" : "=f"(lo), "=f"(hi) : "l"(v));
}

// ---------------- kernel 1: 1x1 conv (3->8) + leaky relu, channels-last ----------------
__global__ void k_conv1(const float* __restrict__ x,
                        const float* __restrict__ w1,
                        const float* __restrict__ b1) {
    int idx = blockIdx.x * blockDim.x + threadIdx.x;   // n*65536 + h*256 + w
    if (idx >= NB * HH * WW) return;
    int n  = idx >> 16;
    int hw = idx & 0xFFFF;
    float x0 = x[(n * 3 + 0) * 65536 + hw];
    float x1 = x[(n * 3 + 1) * 65536 + hw];
    float x2 = x[(n * 3 + 2) * 65536 + hw];
    float v[8];
#pragma unroll
    for (int c = 0; c < 8; c++) {
        float t = __ldg(&w1[c * 3 + 0]) * x0 + __ldg(&w1[c * 3 + 1]) * x1 +
                  __ldg(&w1[c * 3 + 2]) * x2 + __ldg(&b1[c]);
        v[c] = t >= 0.f ? t : 0.1f * t;
    }
    float4* o = (float4*)(g_y + (size_t)idx * 8);
    o[0] = make_float4(v[0], v[1], v[2], v[3]);
    o[1] = make_float4(v[4], v[5], v[6], v[7]);
}

// ---------------- kernel 2: 3x3 stride-2 conv (8->27) + bias; sigmoid on mask ----------
__global__ void k_offset(const float* __restrict__ ow, const float* __restrict__ ob) {
    __shared__ float ws[27 * 9 * 8];   // [oc][tap][ic]
    int tid = threadIdx.x;
    for (int i = tid; i < 1944; i += 256) {
        int oc = i / 72;
        int rem = i - oc * 72;
        int ic = rem / 9;
        int tap = rem - ic * 9;
        ws[(oc * 9 + tap) * 8 + ic] = ow[i];
    }
    __syncthreads();

    int idx = blockIdx.x * 256 + tid;            // n*16384 + sp
    int n = idx >> 14;
    int sp = idx & 16383;
    int ho = sp >> 7, wo = sp & 127;

    float acc[27];
#pragma unroll
    for (int c = 0; c < 27; c++) acc[c] = 0.f;

#pragma unroll 1
    for (int kh = 0; kh < 3; kh++) {
        int hy = 2 * ho - 1 + kh;
        if ((unsigned)hy >= HH) continue;
#pragma unroll 1
        for (int kw = 0; kw < 3; kw++) {
            int wx = 2 * wo - 1 + kw;
            if ((unsigned)wx >= WW) continue;
            const float4* yp = (const float4*)(g_y + ((size_t)((n * HH + hy) * WW + wx)) * 8);
            float4 u = yp[0], v = yp[1];
            int tap = kh * 3 + kw;
#pragma unroll
            for (int oc = 0; oc < 27; oc++) {
                const float4* wp = (const float4*)(ws + (oc * 9 + tap) * 8);
                float4 a = wp[0], b = wp[1];
                acc[oc] += u.x * a.x + u.y * a.y + u.z * a.z + u.w * a.w +
                           v.x * b.x + v.y * b.y + v.z * b.z + v.w * b.w;
            }
        }
    }

    float* op = g_off + (size_t)n * 27 * 16384 + sp;
#pragma unroll
    for (int c = 0; c < 27; c++) {
        float v = acc[c] + __ldg(&ob[c]);
        if (c >= 18) v = 1.f / (1.f + __expf(-v));   // sigmoid for mask channels
        op[c * 16384] = v;
    }
}

// ---------------- kernel 3: deformable sampling + GEMM (persistent CTAs) --------------
// Grid = 296 = 2 channel-halves x 148 slices. Each block holds W-half [72][256] in smem.
// Per 32-position tile: phase A builds colsT [72][32] (kk = c*9+k), phase B does
// 32x256 GEMM with f32x2-packed FMAs (thread tile 4 pos x 8 ch).
__global__ void __launch_bounds__(256, 2)
k_dcn(const float* __restrict__ dw, float* __restrict__ out) {
    extern __shared__ float sm[];
    float* Ws    = sm;                // [72][256]  (kk-major)
    float* colsT = sm + 72 * 256;     // [72][32]

    int tid = threadIdx.x;
    int half = blockIdx.x & 1;
    int slice = blockIdx.x >> 1;

    // load this block's 256-channel half of W, transposed to [kk][oc_local]
    {
        const float* src = dw + (size_t)(half * 256 + tid) * 72;
#pragma unroll
        for (int kk = 0; kk < 72; kk++) Ws[kk * 256 + tid] = src[kk];
    }

    int pos_g = tid & 7;              // 8 groups of 4 positions
    int ch_g = tid >> 3;              // 32 groups of 8 channels
    const float* ap = colsT + pos_g * 4;
    const float* bp = Ws + ch_g * 8;

    for (int tile = slice; tile < NTILES; tile += NSLICE) {
        int pbase = tile << 5;
        int n = pbase >> 14;
        int spbase = pbase & 16383;

        __syncthreads();   // prior GEMM finished reading colsT (and Ws visible on iter 0)

        // ---- phase A: bilinear sampling, 288 (pos,k) tasks ----
        for (int t = tid; t < 288; t += 256) {
            int pos = t & 31;
            int k = t >> 5;                    // 0..8
            int sp = spbase + pos;
            int ho = sp >> 7, wo = sp & 127;
            const float* offp = g_off + (size_t)n * 27 * 16384 + sp;
            float dy = offp[(2 * k) * 16384];
            float dx = offp[(2 * k + 1) * 16384];
            float m  = offp[(18 + k) * 16384];
            int ky = k / 3;
            int kx = k - ky * 3;
            float py = (float)(2 * ho - 1 + ky) + dy;
            float px = (float)(2 * wo - 1 + kx) + dx;
            float y0f = floorf(py), x0f = floorf(px);
            float fy = py - y0f, fx = px - x0f;
            int y0 = (int)y0f, x0 = (int)x0f;
            float wy0 = 1.f - fy, wx0 = 1.f - fx;

            float a0 = 0, a1 = 0, a2 = 0, a3 = 0, a4 = 0, a5 = 0, a6 = 0, a7 = 0;
#pragma unroll
            for (int oy = 0; oy < 2; oy++) {
                int yy = y0 + oy;
                if ((unsigned)yy >= HH) continue;
                float wy = oy ? fy : wy0;
#pragma unroll
                for (int ox = 0; ox < 2; ox++) {
                    int xx = x0 + ox;
                    if ((unsigned)xx >= WW) continue;
                    float wgt = wy * (ox ? fx : wx0);
                    const float4* p = (const float4*)(g_y + ((size_t)((n * HH + yy) * WW + xx)) * 8);
                    float4 u = p[0], v = p[1];
                    a0 += wgt * u.x; a1 += wgt * u.y; a2 += wgt * u.z; a3 += wgt * u.w;
                    a4 += wgt * v.x; a5 += wgt * v.y; a6 += wgt * v.z; a7 += wgt * v.w;
                }
            }
            float* cw = colsT + k * 32 + pos;  // row kk = c*9+k, stride per c = 9*32
            cw[0 * 288] = a0 * m;
            cw[1 * 288] = a1 * m;
            cw[2 * 288] = a2 * m;
            cw[3 * 288] = a3 * m;
            cw[4 * 288] = a4 * m;
            cw[5 * 288] = a5 * m;
            cw[6 * 288] = a6 * m;
            cw[7 * 288] = a7 * m;
        }
        __syncthreads();

        // ---- phase B: 32x256 GEMM, f32x2 packed ----
        u64 acc[4][4];
#pragma unroll
        for (int i = 0; i < 4; i++)
#pragma unroll
            for (int j = 0; j < 4; j++) acc[i][j] = 0ull;

#pragma unroll 8
        for (int kk = 0; kk < 72; kk++) {
            float4 av = *(const float4*)(ap + kk * 32);
            u64 A0 = pack2(av.x, av.x);
            u64 A1 = pack2(av.y, av.y);
            u64 A2 = pack2(av.z, av.z);
            u64 A3 = pack2(av.w, av.w);
            ulonglong2 q0 = *(const ulonglong2*)(bp + kk * 256);
            ulonglong2 q1 = *(const ulonglong2*)(bp + kk * 256 + 4);
            fma2(acc[0][0], A0, q0.x); fma2(acc[0][1], A0, q0.y);
            fma2(acc[0][2], A0, q1.x); fma2(acc[0][3], A0, q1.y);
            fma2(acc[1][0], A1, q0.x); fma2(acc[1][1], A1, q0.y);
            fma2(acc[1][2], A1, q1.x); fma2(acc[1][3], A1, q1.y);
            fma2(acc[2][0], A2, q0.x); fma2(acc[2][1], A2, q0.y);
            fma2(acc[2][2], A2, q1.x); fma2(acc[2][3], A2, q1.y);
            fma2(acc[3][0], A3, q0.x); fma2(acc[3][1], A3, q0.y);
            fma2(acc[3][2], A3, q1.x); fma2(acc[3][3], A3, q1.y);
        }

        // ---- store: 8 channels x 4 consecutive positions (float4) ----
        float lo[4][4], hi[4][4];
#pragma unroll
        for (int i = 0; i < 4; i++)
#pragma unroll
            for (int j = 0; j < 4; j++) unpack2(acc[i][j], lo[i][j], hi[i][j]);

        size_t outbase = ((size_t)(n * 512 + half * 256 + ch_g * 8)) * 16384 +
                         (size_t)(spbase + pos_g * 4);
#pragma unroll
        for (int j = 0; j < 8; j++) {
            int jp = j >> 1;
            float4 vv = (j & 1)
                ? make_float4(hi[0][jp], hi[1][jp], hi[2][jp], hi[3][jp])
                : make_float4(lo[0][jp], lo[1][jp], lo[2][jp], lo[3][jp]);
            *(float4*)(out + outbase + (size_t)j * 16384) = vv;
        }
    }
}

// ---------------- launch ----------------
extern "C" void kernel_launch(void* const* d_in, const int* in_sizes, int n_in,
                              void* d_out, int out_size) {
    const float* x  = (const float*)d_in[0];
    const float* w1 = (const float*)d_in[1];
    const float* b1 = (const float*)d_in[2];
    const float* ow = (const float*)d_in[3];
    const float* ob = (const float*)d_in[4];
    const float* dw = (const float*)d_in[5];
    float* out = (float*)d_out;

    k_conv1<<<(NB * HH * WW + 255) / 256, 256>>>(x, w1, b1);
    k_offset<<<NPOS / 256, 256>>>(ow, ob);

    int smem = (72 * 256 + 72 * 32) * (int)sizeof(float);   // 82944 B
    cudaFuncSetAttribute(k_dcn, cudaFuncAttributeMaxDynamicSharedMemorySize, smem);
    k_dcn<<<2 * NSLICE, 256, smem>>>(dw, out);
}